// round 6
// baseline (speedup 1.0000x reference)
#include <cuda_runtime.h>
#include <cuda_bf16.h>
#include <cstdint>

// AttentionBlock fused kernel, sm_103a. Round 4:
// Algebraic fusion: M8=Wq@Wk^T, W9=Wv@Wo precomputed; block becomes
//   G=X@M8; S=G@X^T(+c_j); P=softmax; T=P@X; out=T@W9+b9+x.
// Halves tensor FLOPs vs R3. mma.sync engine, 2 CTAs/SM.

#define SEQ   64
#define CH    256
#define LDH   264   // bf16 tile row stride in halves
#define LDP   72    // bf16 P tile stride

__device__ __nv_bfloat16 g_M8[CH * CH];   // Wq @ Wk^T   [a][b]
__device__ __nv_bfloat16 g_W9[CH * CH];   // Wv @ Wo     [a][b]
__device__ float g_b9[CH];                // bv @ Wo + bo
__device__ float g_w8[CH];                // Wk @ bq
__device__ float g_s8;                    // bk . bq

// ---- setup: fused weight products (fp32 accum, bf16 out) ----
__global__ void setup_gemm_kernel(const float* __restrict__ Wq, const float* __restrict__ Wk,
                                  const float* __restrict__ Wv, const float* __restrict__ Wo) {
    __shared__ float As[32][33];
    __shared__ float Bs[32][33];
    const int tid = threadIdx.x;
    const int tx = tid & 31, ty = tid >> 5;
    const int a0 = blockIdx.y * 32, b0 = blockIdx.x * 32;
    const int z = blockIdx.z;
    const float* A = z ? Wv : Wq;

    float acc[4] = {0.f, 0.f, 0.f, 0.f};
    for (int d0 = 0; d0 < CH; d0 += 32) {
        {   // stage A[i][j] = A[a0+i][d0+j]  (coalesced)
            int i = tid >> 3, j = (tid & 7) * 4;
            float4 v = *(const float4*)(A + (a0 + i) * CH + d0 + j);
            As[i][j] = v.x; As[i][j + 1] = v.y; As[i][j + 2] = v.z; As[i][j + 3] = v.w;
        }
        if (z == 0) {   // Bs[dd][c] = Wk[b0+c][d0+dd]
            int i = tid >> 3, j = (tid & 7) * 4;
            float4 v = *(const float4*)(Wk + (b0 + i) * CH + d0 + j);
            Bs[j][i] = v.x; Bs[j + 1][i] = v.y; Bs[j + 2][i] = v.z; Bs[j + 3][i] = v.w;
        } else {        // Bs[dd][c] = Wo[d0+dd][b0+c]
            int j = tid >> 3, i = (tid & 7) * 4;
            float4 v = *(const float4*)(Wo + (d0 + j) * CH + b0 + i);
            Bs[j][i] = v.x; Bs[j][i + 1] = v.y; Bs[j][i + 2] = v.z; Bs[j][i + 3] = v.w;
        }
        __syncthreads();
        #pragma unroll
        for (int dd = 0; dd < 32; dd++) {
            float b = Bs[dd][tx];
            #pragma unroll
            for (int r = 0; r < 4; r++)
                acc[r] += As[ty + 8 * r][dd] * b;
        }
        __syncthreads();
    }
    __nv_bfloat16* dst = z ? g_W9 : g_M8;
    #pragma unroll
    for (int r = 0; r < 4; r++)
        dst[(a0 + ty + 8 * r) * CH + b0 + tx] = __float2bfloat16(acc[r]);
}

__global__ void setup_vec_kernel(const float* __restrict__ Wk, const float* __restrict__ Wo,
                                 const float* __restrict__ bq, const float* __restrict__ bk,
                                 const float* __restrict__ bv, const float* __restrict__ bo) {
    int c = threadIdx.x;
    float w8 = 0.f, b9 = 0.f;
    for (int d = 0; d < CH; d++) {
        w8 += Wk[c * CH + d] * bq[d];
        b9 += bv[d] * Wo[d * CH + c];
    }
    g_w8[c] = w8;
    g_b9[c] = b9 + bo[c];
    if (c == 0) {
        float s = 0.f;
        for (int d = 0; d < CH; d++) s += bk[d] * bq[d];
        g_s8 = s;
    }
}

// ---- mma.sync helpers ----
__device__ __forceinline__ uint32_t smem_u32(const void* p) {
    return (uint32_t)__cvta_generic_to_shared(p);
}
__device__ __forceinline__ void ldm_x4(uint32_t addr, uint32_t& a0, uint32_t& a1,
                                       uint32_t& a2, uint32_t& a3) {
    asm volatile("ldmatrix.sync.aligned.m8n8.x4.shared.b16 {%0,%1,%2,%3}, [%4];"
                 : "=r"(a0), "=r"(a1), "=r"(a2), "=r"(a3) : "r"(addr));
}
__device__ __forceinline__ void ldm_x4t(uint32_t addr, uint32_t& b0, uint32_t& b1,
                                        uint32_t& b2, uint32_t& b3) {
    asm volatile("ldmatrix.sync.aligned.m8n8.x4.trans.shared.b16 {%0,%1,%2,%3}, [%4];"
                 : "=r"(b0), "=r"(b1), "=r"(b2), "=r"(b3) : "r"(addr));
}
__device__ __forceinline__ void mma_bf16(float c[4],
                                         uint32_t a0, uint32_t a1, uint32_t a2, uint32_t a3,
                                         uint32_t b0, uint32_t b1) {
    asm volatile("mma.sync.aligned.m16n8k16.row.col.f32.bf16.bf16.f32 "
                 "{%0,%1,%2,%3}, {%4,%5,%6,%7}, {%8,%9}, {%0,%1,%2,%3};"
                 : "+f"(c[0]), "+f"(c[1]), "+f"(c[2]), "+f"(c[3])
                 : "r"(a0), "r"(a1), "r"(a2), "r"(a3), "r"(b0), "r"(b1));
}
__device__ __forceinline__ void cp16(void* smem, const void* gmem) {
    asm volatile("cp.async.cg.shared.global [%0], [%1], 16;"
                 :: "r"(smem_u32(smem)), "l"(gmem));
}

// Stream a [32 k][256 n] bf16 weight chunk into smem (strided LDH rows).
__device__ __forceinline__ void load_w_chunk32(__nv_bfloat16* dst,
                                               const __nv_bfloat16* src, int tid) {
    #pragma unroll
    for (int i = 0; i < 4; i++) {
        int j = tid + i * 256;     // 1024 x 16B
        cp16(dst + (j >> 5) * LDH + (j & 31) * 8, src + j * 8);
    }
    asm volatile("cp.async.commit_group;");
}

// Core chunked GEMM: acc[32x64 warp tile] = A[64x256](smem) @ W[256x256](gmem).
__device__ __forceinline__ void gemm_w(const __nv_bfloat16* __restrict__ Wg,
                                       const __nv_bfloat16* sA, int ldA,
                                       __nv_bfloat16* sW0, __nv_bfloat16* sW1,
                                       float acc[2][8][4],
                                       int tid, int lane, int r0, int nb) {
    #pragma unroll
    for (int mt = 0; mt < 2; mt++)
        #pragma unroll
        for (int nt = 0; nt < 8; nt++)
            acc[mt][nt][0] = acc[mt][nt][1] = acc[mt][nt][2] = acc[mt][nt][3] = 0.f;

    load_w_chunk32(sW0, Wg, tid);
    #pragma unroll 1
    for (int kc = 0; kc < 8; kc++) {
        __nv_bfloat16* wbuf = (kc & 1) ? sW1 : sW0;
        if (kc < 7) {
            load_w_chunk32((kc & 1) ? sW0 : sW1, Wg + (kc + 1) * 32 * CH, tid);
            asm volatile("cp.async.wait_group 1;");
        } else {
            asm volatile("cp.async.wait_group 0;");
        }
        __syncthreads();
        #pragma unroll
        for (int ks = 0; ks < 2; ks++) {
            int kof = kc * 32 + ks * 16;
            uint32_t a[2][4];
            #pragma unroll
            for (int mt = 0; mt < 2; mt++)
                ldm_x4(smem_u32(sA + (r0 + mt * 16 + (lane & 15)) * ldA
                                + kof + ((lane >> 4) << 3)),
                       a[mt][0], a[mt][1], a[mt][2], a[mt][3]);
            #pragma unroll
            for (int nt16 = 0; nt16 < 4; nt16++) {
                uint32_t b0, b1, b2, b3;
                ldm_x4t(smem_u32(wbuf + (ks * 16 + (lane & 15)) * LDH
                                 + nb + nt16 * 16 + ((lane >> 4) << 3)),
                        b0, b1, b2, b3);
                #pragma unroll
                for (int mt = 0; mt < 2; mt++) {
                    mma_bf16(acc[mt][2 * nt16],     a[mt][0], a[mt][1], a[mt][2], a[mt][3], b0, b1);
                    mma_bf16(acc[mt][2 * nt16 + 1], a[mt][0], a[mt][1], a[mt][2], a[mt][3], b2, b3);
                }
            }
        }
        __syncthreads();
    }
}

// SMEM: sX 33792 + sG 33792 + sW0/sW1 33792 + sP 9216 + sC 256 + sBias 1024 = 111872
#define SMEM_BYTES 111872

__global__ void __launch_bounds__(256, 2)
attn_kernel(const float* __restrict__ x, float* __restrict__ out)
{
    extern __shared__ char smem_raw[];
    __nv_bfloat16* sX  = (__nv_bfloat16*)smem_raw;
    __nv_bfloat16* sG  = sX + SEQ * LDH;
    __nv_bfloat16* sW0 = sG + SEQ * LDH;
    __nv_bfloat16* sW1 = sW0 + 32 * LDH;
    __nv_bfloat16* sP  = sW1 + 32 * LDH;
    float*         sC  = (float*)(sP + SEQ * LDP);
    float*      sBias  = sC + SEQ;

    const int tid  = threadIdx.x;
    const int wid  = tid >> 5;
    const int lane = tid & 31;
    const int grp  = lane >> 2;
    const int tig  = lane & 3;
    const int bh   = blockIdx.x;

    const float* xrow = x   + (size_t)bh * SEQ * CH;
    float*       orow = out + (size_t)bh * SEQ * CH;

    // ---------------- Phase 0: bias + x tile (fp32 -> bf16) ----------------
    sBias[tid] = g_b9[tid];
    {
        const float4* xv = (const float4*)xrow;
        #pragma unroll
        for (int t = 0; t < 16; t++) {
            int i = tid + t * 256;             // 4096 float4
            int row = i >> 6;
            int colf = (i & 63) * 4;
            float4 v = xv[i];
            __nv_bfloat162* d = (__nv_bfloat162*)(sX + row * LDH + colf);
            d[0] = __floats2bfloat162_rn(v.x, v.y);
            d[1] = __floats2bfloat162_rn(v.z, v.w);
        }
    }
    __syncthreads();

    // c_j = x_j . w8 + s8  (column correction; zero when biases are zero)
    {
        int row = tid >> 2, q = tid & 3;
        const __nv_bfloat16* xr = sX + row * LDH + q * 64;
        float s = 0.f;
        #pragma unroll
        for (int e = 0; e < 64; e++) s += __bfloat162float(xr[e]) * g_w8[q * 64 + e];
        s += __shfl_xor_sync(0xffffffffu, s, 1);
        s += __shfl_xor_sync(0xffffffffu, s, 2);
        if (q == 0) sC[row] = s + g_s8;
    }
    // no sync needed yet: sC consumed after gemm_w's internal syncs

    const int r0 = (wid >> 2) * 32;   // warp's 32 rows (GEMM tiling)
    const int nb = (wid & 3) * 64;    // warp's 64 cols

    float acc[2][8][4];

    // ---------------- G = X @ M8 -> sG ----------------
    gemm_w(g_M8, sX, LDH, sW0, sW1, acc, tid, lane, r0, nb);
    #pragma unroll
    for (int mt = 0; mt < 2; mt++)
        #pragma unroll
        for (int nt = 0; nt < 8; nt++) {
            int col = nb + nt * 8 + tig * 2;
            int ra = r0 + mt * 16 + grp;
            *(__nv_bfloat162*)(sG + ra * LDH + col) =
                __floats2bfloat162_rn(acc[mt][nt][0], acc[mt][nt][1]);
            *(__nv_bfloat162*)(sG + (ra + 8) * LDH + col) =
                __floats2bfloat162_rn(acc[mt][nt][2], acc[mt][nt][3]);
        }
    __syncthreads();

    // ---------------- S = (G X^T + c_j)*scale, softmax -> P (warps 0-3) ----
    if (wid < 4) {
        const int r0s = wid * 16;     // 16 rows, all 64 cols
        float sa[8][4];
        #pragma unroll
        for (int nt = 0; nt < 8; nt++)
            sa[nt][0] = sa[nt][1] = sa[nt][2] = sa[nt][3] = 0.f;
        #pragma unroll
        for (int ks = 0; ks < 16; ks++) {
            uint32_t a0, a1, a2, a3;
            ldm_x4(smem_u32(sG + (r0s + (lane & 15)) * LDH + ks * 16 + ((lane >> 4) << 3)),
                   a0, a1, a2, a3);
            #pragma unroll
            for (int nt16 = 0; nt16 < 4; nt16++) {
                uint32_t b0, b1, b2, b3;
                // non-trans x4 on row-major X -> col-major B frags (k=channel)
                ldm_x4(smem_u32(sX + (nt16 * 16 + ((lane >> 4) << 3) + (lane & 7)) * LDH
                                + ks * 16 + (((lane >> 3) & 1) << 3)),
                       b0, b1, b2, b3);
                mma_bf16(sa[2 * nt16],     a0, a1, a2, a3, b0, b1);
                mma_bf16(sa[2 * nt16 + 1], a0, a1, a2, a3, b2, b3);
            }
        }
        const float SCALE = 1.0f / (256.0f * 16.0f * 0.70710678118654752f);
        float v0[16], v1[16];
        #pragma unroll
        for (int nt = 0; nt < 8; nt++) {
            int col = nt * 8 + tig * 2;
            float c0 = sC[col], c1 = sC[col + 1];
            v0[2 * nt] = (sa[nt][0] + c0) * SCALE; v0[2 * nt + 1] = (sa[nt][1] + c1) * SCALE;
            v1[2 * nt] = (sa[nt][2] + c0) * SCALE; v1[2 * nt + 1] = (sa[nt][3] + c1) * SCALE;
        }
        float m0 = v0[0], m1 = v1[0];
        #pragma unroll
        for (int i = 1; i < 16; i++) { m0 = fmaxf(m0, v0[i]); m1 = fmaxf(m1, v1[i]); }
        m0 = fmaxf(m0, __shfl_xor_sync(0xffffffffu, m0, 1));
        m0 = fmaxf(m0, __shfl_xor_sync(0xffffffffu, m0, 2));
        m1 = fmaxf(m1, __shfl_xor_sync(0xffffffffu, m1, 1));
        m1 = fmaxf(m1, __shfl_xor_sync(0xffffffffu, m1, 2));
        float s0 = 0.f, s1 = 0.f;
        #pragma unroll
        for (int i = 0; i < 16; i++) {
            v0[i] = __expf(v0[i] - m0); s0 += v0[i];
            v1[i] = __expf(v1[i] - m1); s1 += v1[i];
        }
        s0 += __shfl_xor_sync(0xffffffffu, s0, 1);
        s0 += __shfl_xor_sync(0xffffffffu, s0, 2);
        s1 += __shfl_xor_sync(0xffffffffu, s1, 1);
        s1 += __shfl_xor_sync(0xffffffffu, s1, 2);
        float i0 = 1.0f / s0, i1 = 1.0f / s1;
        int ra = r0s + grp, rb = ra + 8;
        #pragma unroll
        for (int nt = 0; nt < 8; nt++) {
            *(__nv_bfloat162*)(sP + ra * LDP + nt * 8 + tig * 2) =
                __floats2bfloat162_rn(v0[2 * nt] * i0, v0[2 * nt + 1] * i0);
            *(__nv_bfloat162*)(sP + rb * LDP + nt * 8 + tig * 2) =
                __floats2bfloat162_rn(v1[2 * nt] * i1, v1[2 * nt + 1] * i1);
        }
    }
    __syncthreads();

    // ---------------- T = P @ X -> sG (G dead after S) ----------------
    {
        #pragma unroll
        for (int mt = 0; mt < 2; mt++)
            #pragma unroll
            for (int nt = 0; nt < 8; nt++)
                acc[mt][nt][0] = acc[mt][nt][1] = acc[mt][nt][2] = acc[mt][nt][3] = 0.f;
        #pragma unroll
        for (int ks = 0; ks < 4; ks++) {
            uint32_t a[2][4];
            #pragma unroll
            for (int mt = 0; mt < 2; mt++)
                ldm_x4(smem_u32(sP + (r0 + mt * 16 + (lane & 15)) * LDP
                                + ks * 16 + ((lane >> 4) << 3)),
                       a[mt][0], a[mt][1], a[mt][2], a[mt][3]);
            #pragma unroll
            for (int nt16 = 0; nt16 < 4; nt16++) {
                uint32_t b0, b1, b2, b3;
                ldm_x4t(smem_u32(sX + (ks * 16 + (lane & 15)) * LDH
                                 + nb + nt16 * 16 + ((lane >> 4) << 3)),
                        b0, b1, b2, b3);
                #pragma unroll
                for (int mt = 0; mt < 2; mt++) {
                    mma_bf16(acc[mt][2 * nt16],     a[mt][0], a[mt][1], a[mt][2], a[mt][3], b0, b1);
                    mma_bf16(acc[mt][2 * nt16 + 1], a[mt][0], a[mt][1], a[mt][2], a[mt][3], b2, b3);
                }
            }
        }
        __syncthreads();   // all phase-B reads of sG complete
        #pragma unroll
        for (int mt = 0; mt < 2; mt++)
            #pragma unroll
            for (int nt = 0; nt < 8; nt++) {
                int col = nb + nt * 8 + tig * 2;
                int ra = r0 + mt * 16 + grp;
                *(__nv_bfloat162*)(sG + ra * LDH + col) =
                    __floats2bfloat162_rn(acc[mt][nt][0], acc[mt][nt][1]);
                *(__nv_bfloat162*)(sG + (ra + 8) * LDH + col) =
                    __floats2bfloat162_rn(acc[mt][nt][2], acc[mt][nt][3]);
            }
    }
    __syncthreads();

    // ---------------- out = T @ W9 + b9 + x ----------------
    gemm_w(g_W9, sG, LDH, sW0, sW1, acc, tid, lane, r0, nb);
    #pragma unroll
    for (int mt = 0; mt < 2; mt++)
        #pragma unroll
        for (int nt = 0; nt < 8; nt++) {
            int col = nb + nt * 8 + tig * 2;
            float b0v = sBias[col], b1v = sBias[col + 1];
            int ra = r0 + mt * 16 + grp, rb = ra + 8;
            float2 xa = *(const float2*)(xrow + ra * CH + col);
            float2 xb = *(const float2*)(xrow + rb * CH + col);
            *(float2*)(orow + ra * CH + col) =
                make_float2(acc[mt][nt][0] + b0v + xa.x, acc[mt][nt][1] + b1v + xa.y);
            *(float2*)(orow + rb * CH + col) =
                make_float2(acc[mt][nt][2] + b0v + xb.x, acc[mt][nt][3] + b1v + xb.y);
        }
}

extern "C" void kernel_launch(void* const* d_in, const int* in_sizes, int n_in,
                              void* d_out, int out_size) {
    const float* x  = (const float*)d_in[0];
    const float* Wq = (const float*)d_in[1];
    const float* bq = (const float*)d_in[2];
    const float* Wk = (const float*)d_in[3];
    const float* bk = (const float*)d_in[4];
    const float* Wv = (const float*)d_in[5];
    const float* bv = (const float*)d_in[6];
    const float* Wo = (const float*)d_in[7];
    const float* bo = (const float*)d_in[8];
    float* out = (float*)d_out;

    dim3 g8(8, 8, 2);
    setup_gemm_kernel<<<g8, 256>>>(Wq, Wk, Wv, Wo);
    setup_vec_kernel<<<1, 256>>>(Wk, Wo, bq, bk, bv, bo);

    cudaFuncSetAttribute(attn_kernel, cudaFuncAttributeMaxDynamicSharedMemorySize, SMEM_BYTES);
    attn_kernel<<<2048, 256, SMEM_BYTES>>>(x, out);
}